// round 2
// baseline (speedup 1.0000x reference)
#include <cuda_runtime.h>
#include <cuda_bf16.h>
#include <cstdint>

#define NPROT 100000
#define NSUB  50000
#define HDIM  64
#define PDIM  1024
#define SDIM  512
#define EPROT 3200000
#define ESUB  1600000
#define ELNK  2000000

// ---------------- scratch (static device allocation; no cudaMalloc) --------
#define OFF_P0 0L
#define OFF_P1 (OFF_P0 + (long)NPROT*64)
#define OFF_P2 (OFF_P1 + (long)NPROT*64)
#define OFF_S0 (OFF_P2 + (long)NPROT*64)
#define OFF_S1 (OFF_S0 + (long)NSUB*64)
#define OFF_S2 (OFF_S1 + (long)NSUB*64)
#define OFF_DP (OFF_S2 + (long)NSUB*64)
#define OFF_DS (OFF_DP + NPROT)
#define OFF_MP (OFF_DS + NSUB)
#define OFF_MS (OFF_MP + 64*64)
#define OFF_C  (OFF_MS + 64*64)
#define SCRATCH_TOTAL (OFF_C + 64)

__device__ __align__(256) float g_scratch[SCRATCH_TOTAL];

// ---------------- small elementwise kernels --------------------------------
__global__ void k_fill1(float* p, int n) {
    int i = blockIdx.x * blockDim.x + threadIdx.x;
    if (i < n) p[i] = 1.0f;
}

__global__ void k_count_deg(const int* __restrict__ dst, int E, float* __restrict__ deg) {
    int i = blockIdx.x * blockDim.x + threadIdx.x;
    if (i < E) atomicAdd(&deg[dst[i]], 1.0f);
}

__global__ void k_rsqrt(float* p, int n) {
    int i = blockIdx.x * blockDim.x + threadIdx.x;
    if (i < n) p[i] = rsqrtf(p[i]);
}

// out[row,:] = dinv[row] * acc[row,:] + bias[:]
__global__ void k_finish(const float* __restrict__ acc, const float* __restrict__ dinv,
                         const float* __restrict__ bias, float* __restrict__ out, int N) {
    int i = blockIdx.x * blockDim.x + threadIdx.x;   // over N*16 float4s
    if (i >= N * 16) return;
    int row = i >> 4;
    int c4 = (i & 15) << 2;
    float d = dinv[row];
    float4 a = *(const float4*)&acc[(long)row * 64 + c4];
    float4 b = *(const float4*)&bias[c4];
    float4 o = make_float4(fmaf(a.x, d, b.x), fmaf(a.y, d, b.y),
                           fmaf(a.z, d, b.z), fmaf(a.w, d, b.w));
    *(float4*)&out[(long)row * 64 + c4] = o;
}

// Mp = (Wproj@Wl1)[0:64,:], Ms = rows 64:128, c = bproj@Wl1 + bl1
__global__ void k_prep_mlp(const float* __restrict__ Wproj, const float* __restrict__ bproj,
                           const float* __restrict__ Wl1, const float* __restrict__ bl1,
                           float* __restrict__ Mp, float* __restrict__ Ms, float* __restrict__ c) {
    int gid = blockIdx.x * blockDim.x + threadIdx.x;
    if (gid < 128 * 64) {
        int a = gid >> 6, j = gid & 63;
        float s = 0.f;
        #pragma unroll 4
        for (int t = 0; t < 128; t++) s = fmaf(Wproj[a * 128 + t], Wl1[t * 64 + j], s);
        if (a < 64) Mp[a * 64 + j] = s;
        else        Ms[(a - 64) * 64 + j] = s;
    }
    if (gid < 64) {
        float s = bl1[gid];
        #pragma unroll 4
        for (int t = 0; t < 128; t++) s = fmaf(bproj[t], Wl1[t * 64 + gid], s);
        c[gid] = s;
    }
}

// ---------------- GEMM: out[M,64] = (X[M,K] @ W[K,64]) * dinv[row] ---------
template <int K>
__global__ void k_gemm_n64(const float* __restrict__ X, const float* __restrict__ W,
                           const float* __restrict__ dinv,
                           float* __restrict__ outH, float* __restrict__ outAcc, int M) {
    __shared__ float Xs[64][16];
    __shared__ float Ws[16][64];
    const int tid = threadIdx.x;           // 256 threads
    const int tx = tid & 15;               // col group (4 cols)
    const int ty = tid >> 4;               // row group (rows ty+16i)
    const int row0 = blockIdx.x * 64;

    float acc[4][4];
    #pragma unroll
    for (int i = 0; i < 4; i++)
        #pragma unroll
        for (int j = 0; j < 4; j++) acc[i][j] = 0.f;

    const int lr = tid >> 2;               // X load row 0..63
    const int lc = (tid & 3) << 2;         // X load col4
    const int wr = tid >> 4;               // W load row 0..15
    const int wc = (tid & 15) << 2;        // W load col4

    for (int kk = 0; kk < K; kk += 16) {
        float4 xv = make_float4(0.f, 0.f, 0.f, 0.f);
        if (row0 + lr < M) xv = *(const float4*)&X[(long)(row0 + lr) * K + kk + lc];
        *(float4*)&Xs[lr][lc] = xv;
        *(float4*)&Ws[wr][wc] = *(const float4*)&W[(long)(kk + wr) * 64 + wc];
        __syncthreads();
        #pragma unroll
        for (int k = 0; k < 16; k++) {
            float4 wv = *(const float4*)&Ws[k][tx << 2];
            float xr[4];
            #pragma unroll
            for (int i = 0; i < 4; i++) xr[i] = Xs[ty + (i << 4)][k];
            #pragma unroll
            for (int i = 0; i < 4; i++) {
                acc[i][0] = fmaf(xr[i], wv.x, acc[i][0]);
                acc[i][1] = fmaf(xr[i], wv.y, acc[i][1]);
                acc[i][2] = fmaf(xr[i], wv.z, acc[i][2]);
                acc[i][3] = fmaf(xr[i], wv.w, acc[i][3]);
            }
        }
        __syncthreads();
    }

    #pragma unroll
    for (int i = 0; i < 4; i++) {
        int r = row0 + ty + (i << 4);
        if (r < M) {
            float d = dinv ? dinv[r] : 1.0f;
            float4 v = make_float4(acc[i][0] * d, acc[i][1] * d, acc[i][2] * d, acc[i][3] * d);
            *(float4*)&outH[(long)r * 64 + (tx << 2)] = v;
            if (outAcc) *(float4*)&outAcc[(long)r * 64 + (tx << 2)] = v;
        }
    }
}

// ---------------- edge scatter: acc[dst,:] += hs[src,:] --------------------
// 16 threads per edge, 4 floats each; vector reduction to gmem (sm_90+)
__global__ void k_scatter(const int* __restrict__ src, const int* __restrict__ dst,
                          int E, const float* __restrict__ hs, float* __restrict__ acc) {
    int gid = blockIdx.x * blockDim.x + threadIdx.x;
    int e = gid >> 4;
    if (e >= E) return;
    int j = (gid & 15) << 2;
    int s = src[e];
    int d = dst[e];
    float4 v = *(const float4*)&hs[(long)s * 64 + j];
    float* addr = &acc[(long)d * 64 + j];
    asm volatile("red.global.add.v4.f32 [%0], {%1, %2, %3, %4};"
                 :: "l"(addr), "f"(v.x), "f"(v.y), "f"(v.z), "f"(v.w)
                 : "memory");
}

// ---------------- link predictor: out[e] = relu(A[ep]+B[es]+c)@Wl2 + bl2 ---
__global__ void k_link(const int* __restrict__ ep, const int* __restrict__ es,
                       const float* __restrict__ A, const float* __restrict__ B,
                       const float* __restrict__ cvec, const float* __restrict__ wl2,
                       const float* __restrict__ bl2, float* __restrict__ out) {
    int lane = threadIdx.x & 31;
    int half = lane >> 4;
    int sub = lane & 15;
    int warp = (blockIdx.x * blockDim.x + threadIdx.x) >> 5;
    int pair = warp;
    if (pair * 2 >= ELNK) return;
    int e = pair * 2 + half;   // ELNK even -> always valid

    float4 c4 = *(const float4*)&cvec[sub << 2];
    float4 w4 = *(const float4*)&wl2[sub << 2];

    long pi = (long)ep[e];
    long si = (long)es[e];
    float4 a = *(const float4*)&A[pi * 64 + (sub << 2)];
    float4 b = *(const float4*)&B[si * 64 + (sub << 2)];

    float r = fmaxf(a.x + b.x + c4.x, 0.f) * w4.x
            + fmaxf(a.y + b.y + c4.y, 0.f) * w4.y
            + fmaxf(a.z + b.z + c4.z, 0.f) * w4.z
            + fmaxf(a.w + b.w + c4.w, 0.f) * w4.w;

    #pragma unroll
    for (int off = 8; off > 0; off >>= 1)
        r += __shfl_down_sync(0xffffffffu, r, off, 16);

    if (sub == 0) out[e] = r + bl2[0];
}

// ---------------- launch ----------------------------------------------------
extern "C" void kernel_launch(void* const* d_in, const int* in_sizes, int n_in,
                              void* d_out, int out_size) {
    const float* x_p  = (const float*)d_in[0];
    const float* x_s  = (const float*)d_in[1];
    const int*   ei_p = (const int*)d_in[2];   // [2, EPROT] int32
    const int*   ei_s = (const int*)d_in[3];   // [2, ESUB]  int32
    const int*   ep   = (const int*)d_in[4];
    const int*   es   = (const int*)d_in[5];
    const float *Wp1 = (const float*)d_in[6],  *bp1 = (const float*)d_in[7];
    const float *Ws1 = (const float*)d_in[8],  *bs1 = (const float*)d_in[9];
    const float *Wp2 = (const float*)d_in[10], *bp2 = (const float*)d_in[11];
    const float *Ws2 = (const float*)d_in[12], *bs2 = (const float*)d_in[13];
    const float *Wproj = (const float*)d_in[14], *bproj = (const float*)d_in[15];
    const float *Wl1 = (const float*)d_in[16], *bl1 = (const float*)d_in[17];
    const float *Wl2 = (const float*)d_in[18], *bl2 = (const float*)d_in[19];
    float* out = (float*)d_out;

    float* scratch = nullptr;
    cudaGetSymbolAddress((void**)&scratch, g_scratch);
    float* P0 = scratch + OFF_P0;
    float* P1 = scratch + OFF_P1;
    float* P2 = scratch + OFF_P2;
    float* S0 = scratch + OFF_S0;
    float* S1 = scratch + OFF_S1;
    float* S2 = scratch + OFF_S2;
    float* dinvP = scratch + OFF_DP;
    float* dinvS = scratch + OFF_DS;
    float* Mp = scratch + OFF_MP;
    float* Ms = scratch + OFF_MS;
    float* cv = scratch + OFF_C;

    const int T = 256;
    // degrees (self-loop included as initial 1.0)
    k_fill1<<<(NPROT + T - 1) / T, T>>>(dinvP, NPROT);
    k_fill1<<<(NSUB + T - 1) / T, T>>>(dinvS, NSUB);
    k_count_deg<<<(EPROT + T - 1) / T, T>>>(ei_p + EPROT, EPROT, dinvP);
    k_count_deg<<<(ESUB + T - 1) / T, T>>>(ei_s + ESUB, ESUB, dinvS);
    k_rsqrt<<<(NPROT + T - 1) / T, T>>>(dinvP, NPROT);
    k_rsqrt<<<(NSUB + T - 1) / T, T>>>(dinvS, NSUB);

    // fold Wproj/Wl1 into per-node matrices
    k_prep_mlp<<<(128 * 64 + T - 1) / T, T>>>(Wproj, bproj, Wl1, bl1, Mp, Ms, cv);

    const int gP = (NPROT + 63) / 64;
    const int gS = (NSUB + 63) / 64;
    const int scatP = (int)(((long)EPROT * 16 + T - 1) / T);
    const int scatS = (int)(((long)ESUB * 16 + T - 1) / T);
    const int finP = (NPROT * 16 + T - 1) / T;
    const int finS = (NSUB * 16 + T - 1) / T;

    // ---- protein conv1 ----
    k_gemm_n64<PDIM><<<gP, T>>>(x_p, Wp1, dinvP, P1, P2, NPROT);
    k_scatter<<<scatP, T>>>(ei_p, ei_p + EPROT, EPROT, P1, P2);
    k_finish<<<finP, T>>>(P2, dinvP, bp1, P0, NPROT);
    // ---- protein conv2 ----
    k_gemm_n64<HDIM><<<gP, T>>>(P0, Wp2, dinvP, P1, P2, NPROT);
    k_scatter<<<scatP, T>>>(ei_p, ei_p + EPROT, EPROT, P1, P2);
    k_finish<<<finP, T>>>(P2, dinvP, bp2, P0, NPROT);
    // ---- protein A-table: A = z_p @ Mp ----
    k_gemm_n64<HDIM><<<gP, T>>>(P0, Mp, nullptr, P1, nullptr, NPROT);

    // ---- substrate conv1 ----
    k_gemm_n64<SDIM><<<gS, T>>>(x_s, Ws1, dinvS, S1, S2, NSUB);
    k_scatter<<<scatS, T>>>(ei_s, ei_s + ESUB, ESUB, S1, S2);
    k_finish<<<finS, T>>>(S2, dinvS, bs1, S0, NSUB);
    // ---- substrate conv2 ----
    k_gemm_n64<HDIM><<<gS, T>>>(S0, Ws2, dinvS, S1, S2, NSUB);
    k_scatter<<<scatS, T>>>(ei_s, ei_s + ESUB, ESUB, S1, S2);
    k_finish<<<finS, T>>>(S2, dinvS, bs2, S0, NSUB);
    // ---- substrate B-table: B = z_s @ Ms ----
    k_gemm_n64<HDIM><<<gS, T>>>(S0, Ms, nullptr, S1, nullptr, NSUB);

    // ---- link prediction ----
    int linkWarps = ELNK / 2;
    int linkBlocks = (int)(((long)linkWarps * 32 + T - 1) / T);
    k_link<<<linkBlocks, T>>>(ep, es, P1, S1, cv, Wl2, bl2, out);
}